// round 12
// baseline (speedup 1.0000x reference)
#include <cuda_runtime.h>
#include <cstdint>
#include <cstddef>

// Problem dims (fixed)
#define BB   32
#define TT   4096
#define DIN  256
#define HH   256
#define G4   1024   // 4*H

// ---------------- scratch (static device arrays; no allocation) ----------------
__device__ float g_xg[(size_t)BB * TT * G4];   // 512 MB : x @ Wx + b
__device__ float g_hseq[(size_t)BB * TT * HH]; // 128 MB : h_t for all t

// ---------------- PTX helpers ----------------
__device__ __forceinline__ unsigned long long ffma2(unsigned long long a,
                                                    unsigned long long b,
                                                    unsigned long long c) {
    unsigned long long d;
    asm("fma.rn.f32x2 %0, %1, %2, %3;" : "=l"(d) : "l"(a), "l"(b), "l"(c));
    return d;
}
__device__ __forceinline__ unsigned long long addx2(unsigned long long a,
                                                    unsigned long long b) {
    unsigned long long d;
    asm("add.rn.f32x2 %0, %1, %2;" : "=l"(d) : "l"(a), "l"(b));
    return d;
}
__device__ __forceinline__ unsigned long long pk2(float lo, float hi) {
    unsigned long long r;
    asm("mov.b64 %0, {%1,%2};" : "=l"(r) : "f"(lo), "f"(hi));
    return r;
}
__device__ __forceinline__ float2 unpk2(unsigned long long v) {
    float lo, hi;
    asm("mov.b64 {%0,%1}, %2;" : "=f"(lo), "=f"(hi) : "l"(v));
    return make_float2(lo, hi);
}
__device__ __forceinline__ uint32_t s2u(const void* p) {
    return (uint32_t)__cvta_generic_to_shared(p);
}
__device__ __forceinline__ uint32_t mapa_u32(uint32_t addr, uint32_t rank) {
    uint32_t r;
    asm("mapa.shared::cluster.u32 %0, %1, %2;" : "=r"(r) : "r"(addr), "r"(rank));
    return r;
}
// DSMEM tagged push: 8B relaxed store to a peer CTA's SMEM (tear-free, tag+data in one word)
__device__ __forceinline__ void st_clu64(uint32_t addr, unsigned long long v) {
    asm volatile("st.relaxed.cluster.shared::cluster.u64 [%0], %1;"
                 :: "r"(addr), "l"(v) : "memory");
}
// local SMEM poll load (relaxed, cta scope)
__device__ __forceinline__ unsigned long long ld_cta64(uint32_t addr) {
    unsigned long long v;
    asm volatile("ld.relaxed.cta.shared::cta.u64 %0, [%1];"
                 : "=l"(v) : "r"(addr) : "memory");
    return v;
}

// ---------------- fp32 GEMM (f32x2 inner loop): C = A@B + bias ----------------
__global__ void __launch_bounds__(256) sgemm_bias_128(
    const float* __restrict__ A, const float* __restrict__ B,
    const float* __restrict__ bias, float* __restrict__ C,
    int M, int N, int K)
{
    __shared__ __align__(16) float As[8][128];
    __shared__ __align__(16) float Bs[8][128];

    const int tid = threadIdx.x;
    const int bm  = blockIdx.y;
    const int bn  = blockIdx.x;
    const int tx  = tid & 15;
    const int ty  = tid >> 4;

    const int arow = tid >> 1;
    const int ak   = (tid & 1) * 4;
    const int brow = tid >> 5;
    const int bcol = (tid & 31) * 4;

    const float* Aptr = A + (size_t)(bm * 128 + arow) * K + ak;
    const float* Bptr = B + (size_t)brow * N + bn * 128 + bcol;

    unsigned long long acc2[8][4];
#pragma unroll
    for (int i = 0; i < 8; i++)
#pragma unroll
        for (int jp = 0; jp < 4; jp++) acc2[i][jp] = 0ull;

    for (int k0 = 0; k0 < K; k0 += 8) {
        const float4 va = *(const float4*)(Aptr + k0);
        const float4 vb = *(const float4*)(Bptr + (size_t)k0 * N);
        __syncthreads();
        As[ak + 0][arow] = va.x;
        As[ak + 1][arow] = va.y;
        As[ak + 2][arow] = va.z;
        As[ak + 3][arow] = va.w;
        *(float4*)&Bs[brow][bcol] = vb;
        __syncthreads();

#pragma unroll
        for (int k = 0; k < 8; k++) {
            float a0[4], a1[4];
            *(float4*)a0 = *(const float4*)&As[k][ty * 4];
            *(float4*)a1 = *(const float4*)&As[k][64 + ty * 4];
            const ulonglong2 bp0 = *(const ulonglong2*)&Bs[k][tx * 4];
            const ulonglong2 bp1 = *(const ulonglong2*)&Bs[k][64 + tx * 4];
#pragma unroll
            for (int i = 0; i < 4; i++) {
                const unsigned long long ad0 = pk2(a0[i], a0[i]);
                acc2[i][0] = ffma2(ad0, bp0.x, acc2[i][0]);
                acc2[i][1] = ffma2(ad0, bp0.y, acc2[i][1]);
                acc2[i][2] = ffma2(ad0, bp1.x, acc2[i][2]);
                acc2[i][3] = ffma2(ad0, bp1.y, acc2[i][3]);
                const unsigned long long ad1 = pk2(a1[i], a1[i]);
                acc2[i + 4][0] = ffma2(ad1, bp0.x, acc2[i + 4][0]);
                acc2[i + 4][1] = ffma2(ad1, bp0.y, acc2[i + 4][1]);
                acc2[i + 4][2] = ffma2(ad1, bp1.x, acc2[i + 4][2]);
                acc2[i + 4][3] = ffma2(ad1, bp1.y, acc2[i + 4][3]);
            }
        }
    }

    const float* bptr = bias + bn * 128;
    const ulonglong2 bv0 = *(const ulonglong2*)&bptr[tx * 4];
    const ulonglong2 bv1 = *(const ulonglong2*)&bptr[64 + tx * 4];

#pragma unroll
    for (int i = 0; i < 8; i++) {
        const int row = bm * 128 + ((i < 4) ? (ty * 4 + i) : (64 + ty * 4 + (i - 4)));
        ulonglong2 o0, o1;
        o0.x = addx2(acc2[i][0], bv0.x);
        o0.y = addx2(acc2[i][1], bv0.y);
        o1.x = addx2(acc2[i][2], bv1.x);
        o1.y = addx2(acc2[i][3], bv1.y);
        *(ulonglong2*)&C[(size_t)row * N + bn * 128 + tx * 4]      = o0;
        *(ulonglong2*)&C[(size_t)row * N + bn * 128 + 64 + tx * 4] = o1;
    }
}

// ---------------- recurrence: R10 compute + DSMEM tagged-push exchange ---------
// 16 clusters x 8 CTAs; cluster = batch pair (b0,b1), rank j = blockIdx.x%8 owns
// gate-columns colg(c) = (c>>5)*256 + j*32 + (c&31).
// Compute (= R10, fastest so far): warp w owns K-slice [32w,+32); lane loads ONE
// h per batch (coalesced), redistributes via shfl.idx; accumulates 4 cols as
// 2 f32x2 pairs x 2 batches; w2[32][2] persistent (128 regs).
// Reduce: STS red[8][2][128] -> bar -> 256-thread add (+xg) -> gsm -> bar ->
// 64-thread activation (csm SMEM).
// EXCHANGE (new): act thread pushes pk2(h, tag) into ALL 8 peers' SMEM hx
// buffers (st.relaxed.cluster, 8 stores; mapa bases precomputed). Consumers
// poll their OWN SMEM (ld.relaxed.cta, ~29cyc) until both tags >= t+1.
// No mbarrier, no fences; tag travels inside the single 8B word. hx is SMEM ->
// fresh every launch (no global tag reset needed). Parity double-buffered;
// all-ranks poll bounds skew to 1 step so slot reuse is safe.
__global__ void __launch_bounds__(256, 1) __cluster_dims__(8, 1, 1)
lstm_rec(const float* __restrict__ Wh)
{
    const int cta  = blockIdx.x;
    const int grp  = cta >> 3;
    const int j    = cta & 7;                 // == cluster rank
    const int b0   = grp * 2;
    const int tid  = threadIdx.x;
    const int w    = tid >> 5;
    const int lane = tid & 31;

    // reduce mapping: thread t -> (batch rb, column rcol)
    const int rb    = tid >> 7;
    const int rcol  = tid & 127;
    const int rcolg = (rcol >> 5) * 256 + j * 32 + (rcol & 31);

    __shared__ __align__(16) float hs[2][256];        // batch x h
    __shared__ __align__(16) float red[8][2][128];    // warp x batch x col
    __shared__ float gsm[256];
    __shared__ float csm[2][32];
    __shared__ __align__(16) unsigned long long hx[2][256][2];  // slot x hidx x batch

    // persistent packed weights (R10 mapping)
    unsigned long long w2[32][2];
    {
        const int c0  = 4 * lane;
        const int cg0 = (c0 >> 5) * 256 + j * 32 + (c0 & 31);
        const int c2  = c0 + 2;
        const int cg2 = (c2 >> 5) * 256 + j * 32 + (c2 & 31);
#pragma unroll
        for (int k = 0; k < 32; k++) {
            const float* wr = Wh + (size_t)(w * 32 + k) * G4;
            w2[k][0] = pk2(__ldg(&wr[cg0]), __ldg(&wr[cg0 + 1]));
            w2[k][1] = pk2(__ldg(&wr[cg2]), __ldg(&wr[cg2 + 1]));
        }
    }

    // init local state + exchange buffer (SMEM -> fresh each launch)
    hs[0][tid] = 0.f;
    hs[1][tid] = 0.f;
    hx[0][tid][0] = 0ull; hx[0][tid][1] = 0ull;
    hx[1][tid][0] = 0ull; hx[1][tid][1] = 0ull;
    if (tid < 64) csm[tid >> 5][tid & 31] = 0.f;
    __syncthreads();

    // peer base addresses for the hx buffer (one mapa per rank, done once)
    const uint32_t hxu = s2u(hx);
    uint32_t peer[8];
#pragma unroll
    for (int r = 0; r < 8; r++) peer[r] = mapa_u32(hxu, (uint32_t)r);

    // cluster barrier: all hx buffers initialized before anyone may push
    asm volatile("barrier.cluster.arrive.aligned;" ::: "memory");
    asm volatile("barrier.cluster.wait.aligned;" ::: "memory");

    // preload xg for t=0 (reduce mapping)
    float xv = __ldg(&g_xg[((size_t)((b0 + rb) * TT)) * G4 + rcolg]);

    for (int t = 0; t < TT; t++) {
        // ---- outer-product partial GEMV over this warp's K-slice (R10) ----
        const float h0l = hs[0][w * 32 + lane];
        const float h1l = hs[1][w * 32 + lane];
        unsigned long long a00 = 0ull, a01 = 0ull, a10 = 0ull, a11 = 0ull;
#pragma unroll
        for (int k = 0; k < 32; k++) {
            const float s0 = __shfl_sync(0xffffffffu, h0l, k);
            const float s1 = __shfl_sync(0xffffffffu, h1l, k);
            const unsigned long long hb0 = pk2(s0, s0);
            const unsigned long long hb1 = pk2(s1, s1);
            a00 = ffma2(w2[k][0], hb0, a00);
            a01 = ffma2(w2[k][1], hb0, a01);
            a10 = ffma2(w2[k][0], hb1, a10);
            a11 = ffma2(w2[k][1], hb1, a11);
        }
        {
            const float2 u0 = unpk2(a00), u1 = unpk2(a01);
            const float2 v0 = unpk2(a10), v1 = unpk2(a11);
            *(float4*)&red[w][0][4 * lane] = make_float4(u0.x, u0.y, u1.x, u1.y);
            *(float4*)&red[w][1][4 * lane] = make_float4(v0.x, v0.y, v1.x, v1.y);
        }
        __syncthreads();   // red ready; also guards hs reads vs later rewrite

        // ---- cross-warp reduce (+xg) ----
        {
            float s = xv;
#pragma unroll
            for (int r = 0; r < 8; r++) s += red[r][rb][rcol];
            gsm[tid] = s;
        }
        __syncthreads();

        const int   sl   = (t + 1) & 1;
        const float tagf = (float)(t + 1);

        // ---- activation + DSMEM tagged push ----
        if (tid < 64) {
            const int bb = tid >> 5, ll = tid & 31;
            const float* gp = gsm + bb * 128;
            const float gi = gp[ll];
            const float gf = gp[32 + ll];
            const float gg = gp[64 + ll];
            const float go = gp[96 + ll];
            const float cprev = csm[bb][ll];
            const float si = 1.f / (1.f + __expf(-gi));
            const float sf = 1.f / (1.f + __expf(-gf));
            const float so = 1.f / (1.f + __expf(-go));
            const float tg = 2.f / (1.f + __expf(-2.f * gg)) - 1.f;
            const float cn = sf * cprev + si * tg;
            const float tc = 2.f / (1.f + __expf(-2.f * cn)) - 1.f;
            const float hn = so * tc;
            csm[bb][ll] = cn;
            const int hidx = j * 32 + ll;
            if (t + 1 < TT) {
                const unsigned long long word = pk2(hn, tagf);
                const uint32_t off = (uint32_t)((((sl << 8) + hidx) * 2 + bb) * 8);
#pragma unroll
                for (int r = 0; r < 8; r++)
                    st_clu64(peer[r] + off, word);
            }
            g_hseq[((size_t)((b0 + bb) * TT + t)) * HH + hidx] = hn;
        }
        // NO barrier: warps 2-7 go straight to polling while warps 0-1 finish

        if (t + 1 < TT) {
            // prefetch next xg (in flight during the poll)
            xv = __ldg(&g_xg[((size_t)((b0 + rb) * TT + (t + 1))) * G4 + rcolg]);
            // poll OWN SMEM (local LDS) until both tagged words are fresh
            const uint32_t a0 = hxu + (uint32_t)((((sl << 8) + tid) * 2) * 8);
            float2 d0, d1;
            for (;;) {
                const unsigned long long v0 = ld_cta64(a0);
                const unsigned long long v1 = ld_cta64(a0 + 8);
                d0 = unpk2(v0);
                d1 = unpk2(v1);
                if (d0.y >= tagf && d1.y >= tagf) break;
            }
            hs[0][tid] = d0.x;
            hs[1][tid] = d1.x;
            __syncthreads();
        }
    }

    // lifetime: no CTA may exit while peers could still push into its SMEM
    asm volatile("barrier.cluster.arrive.aligned;" ::: "memory");
    asm volatile("barrier.cluster.wait.aligned;" ::: "memory");
}

// ---------------- launch ----------------
extern "C" void kernel_launch(void* const* d_in, const int* in_sizes, int n_in,
                              void* d_out, int out_size)
{
    const float* x  = (const float*)d_in[0];   // [B,T,DIN]
    const float* Wx = (const float*)d_in[1];   // [DIN,4H]
    const float* Wh = (const float*)d_in[2];   // [H,4H]
    const float* b  = (const float*)d_in[3];   // [4H]
    const float* Wo = (const float*)d_in[4];   // [H,DOUT]
    const float* bo = (const float*)d_in[5];   // [DOUT]
    float* out = (float*)d_out;                // [B,T,DOUT]

    float *xg_ptr = nullptr, *hseq_ptr = nullptr;
    cudaGetSymbolAddress((void**)&xg_ptr, g_xg);
    cudaGetSymbolAddress((void**)&hseq_ptr, g_hseq);

    // 1) xg = x @ Wx + b : [131072,256] @ [256,1024]
    {
        dim3 grid(G4 / 128, (BB * TT) / 128);   // (8, 1024)
        sgemm_bias_128<<<grid, 256>>>(x, Wx, b, xg_ptr, BB * TT, G4, DIN);
    }

    // 2) recurrence over 4096 steps (16 clusters x 8 CTAs)
    lstm_rec<<<128, 256>>>(Wh);

    // 3) out = hseq @ Wo + bo : [131072,256] @ [256,256]
    {
        dim3 grid(256 / 128, (BB * TT) / 128);  // (2, 1024)
        sgemm_bias_128<<<grid, 256>>>(hseq_ptr, Wo, bo, out, BB * TT, 256, HH);
    }
}

// round 13
// speedup vs baseline: 1.9671x; 1.9671x over previous
#include <cuda_runtime.h>
#include <cstdint>
#include <cstddef>

// Problem dims (fixed)
#define BB   32
#define TT   4096
#define DIN  256
#define HH   256
#define G4   1024   // 4*H

// ---------------- scratch (static device arrays; no allocation) ----------------
__device__ float g_xg[(size_t)BB * TT * G4];   // 512 MB : x @ Wx + b
__device__ float g_hseq[(size_t)BB * TT * HH]; // 128 MB : h_t for all t
// tagged exchange: [slot][group][hidx][batch] = {h, tag} in one 8B word,
// accessed ONLY with relaxed atomics (spec-guaranteed single-copy atomic).
__device__ unsigned long long g_hx[2][16][256][2];

__global__ void init_kernel() {   // zero tags for graph replays
    const int i = blockIdx.x * 256 + threadIdx.x;   // 16384 u64s
    ((unsigned long long*)g_hx)[i] = 0ull;
}

// ---------------- PTX helpers ----------------
__device__ __forceinline__ unsigned long long ffma2(unsigned long long a,
                                                    unsigned long long b,
                                                    unsigned long long c) {
    unsigned long long d;
    asm("fma.rn.f32x2 %0, %1, %2, %3;" : "=l"(d) : "l"(a), "l"(b), "l"(c));
    return d;
}
__device__ __forceinline__ unsigned long long pk2(float lo, float hi) {
    unsigned long long r;
    asm("mov.b64 %0, {%1,%2};" : "=l"(r) : "f"(lo), "f"(hi));
    return r;
}
__device__ __forceinline__ float2 unpk2(unsigned long long v) {
    float lo, hi;
    asm("mov.b64 {%0,%1}, %2;" : "=f"(lo), "=f"(hi) : "l"(v));
    return make_float2(lo, hi);
}
// relaxed 8B atomics: tear-free by the PTX memory model, no fence cost
__device__ __forceinline__ void st_rlx64(unsigned long long* p, unsigned long long v) {
    asm volatile("st.relaxed.gpu.global.u64 [%0], %1;" :: "l"(p), "l"(v) : "memory");
}
__device__ __forceinline__ unsigned long long ld_rlx64(const unsigned long long* p) {
    unsigned long long v;
    asm volatile("ld.relaxed.gpu.global.u64 %0, [%1];" : "=l"(v) : "l"(p) : "memory");
    return v;
}
// HW tanh (sm_75+): ~1e-5 approx error, single MUFU op
__device__ __forceinline__ float tanhap(float x) {
    float y;
    asm("tanh.approx.f32 %0, %1;" : "=f"(y) : "f"(x));
    return y;
}
__device__ __forceinline__ float sigap(float x) {   // sigmoid via tanh
    return fmaf(0.5f, tanhap(0.5f * x), 0.5f);
}

// ---------------- fp32 GEMM, 2-stage smem pipeline: C = A@B + bias ------------
// BM=128, BN=128, BK=8, 256 threads, 8x8 microtile; double-buffered smem,
// one barrier per K-iter, LDG issued one iteration ahead of its STS.
__global__ void __launch_bounds__(256) sgemm_bias_128(
    const float* __restrict__ A, const float* __restrict__ B,
    const float* __restrict__ bias, float* __restrict__ C,
    int M, int N, int K)
{
    __shared__ __align__(16) float As[2][8][128];
    __shared__ __align__(16) float Bs[2][8][128];

    const int tid = threadIdx.x;
    const int bm  = blockIdx.y;
    const int bn  = blockIdx.x;
    const int tx  = tid & 15;
    const int ty  = tid >> 4;

    const int arow = tid >> 1;
    const int ak   = (tid & 1) * 4;
    const int brow = tid >> 5;
    const int bcol = (tid & 31) * 4;

    const float* Aptr = A + (size_t)(bm * 128 + arow) * K + ak;
    const float* Bptr = B + (size_t)brow * N + bn * 128 + bcol;

    const int NIT = K / 8;

    float4 va = *(const float4*)(Aptr);                 // k0 = 0
    float4 vb = *(const float4*)(Bptr);
    // stage 0
    As[0][ak + 0][arow] = va.x;
    As[0][ak + 1][arow] = va.y;
    As[0][ak + 2][arow] = va.z;
    As[0][ak + 3][arow] = va.w;
    *(float4*)&Bs[0][brow][bcol] = vb;
    if (NIT > 1) {                                      // k0 = 8
        va = *(const float4*)(Aptr + 8);
        vb = *(const float4*)(Bptr + (size_t)8 * N);
    }
    __syncthreads();

    float acc[8][8];
#pragma unroll
    for (int i = 0; i < 8; i++)
#pragma unroll
        for (int jj = 0; jj < 8; jj++) acc[i][jj] = 0.f;

    for (int it = 0; it < NIT; it++) {
        const int cur = it & 1;
        // stage it+1 store (data LDG'd one iter ago), overlaps compute of cur
        if (it + 1 < NIT) {
            const int nxt = cur ^ 1;
            As[nxt][ak + 0][arow] = va.x;
            As[nxt][ak + 1][arow] = va.y;
            As[nxt][ak + 2][arow] = va.z;
            As[nxt][ak + 3][arow] = va.w;
            *(float4*)&Bs[nxt][brow][bcol] = vb;
        }
        if (it + 2 < NIT) {
            va = *(const float4*)(Aptr + (size_t)(it + 2) * 8);
            vb = *(const float4*)(Bptr + (size_t)(it + 2) * 8 * N);
        }
#pragma unroll
        for (int k = 0; k < 8; k++) {
            float a0[4], a1[4], b0v[4], b1v[4];
            *(float4*)a0  = *(const float4*)&As[cur][k][ty * 4];
            *(float4*)a1  = *(const float4*)&As[cur][k][64 + ty * 4];
            *(float4*)b0v = *(const float4*)&Bs[cur][k][tx * 4];
            *(float4*)b1v = *(const float4*)&Bs[cur][k][64 + tx * 4];
#pragma unroll
            for (int i = 0; i < 4; i++) {
#pragma unroll
                for (int jj = 0; jj < 4; jj++) {
                    acc[i][jj]         = fmaf(a0[i], b0v[jj], acc[i][jj]);
                    acc[i][jj + 4]     = fmaf(a0[i], b1v[jj], acc[i][jj + 4]);
                    acc[i + 4][jj]     = fmaf(a1[i], b0v[jj], acc[i + 4][jj]);
                    acc[i + 4][jj + 4] = fmaf(a1[i], b1v[jj], acc[i + 4][jj + 4]);
                }
            }
        }
        __syncthreads();   // single barrier: guards next STS overwrite + visibility
    }

    float bvals[8];
#pragma unroll
    for (int jj = 0; jj < 4; jj++) {
        bvals[jj]     = bias[bn * 128 + tx * 4 + jj];
        bvals[jj + 4] = bias[bn * 128 + 64 + tx * 4 + jj];
    }

#pragma unroll
    for (int i = 0; i < 8; i++) {
        const int row = bm * 128 + ((i < 4) ? (ty * 4 + i) : (64 + ty * 4 + (i - 4)));
        float4 o0, o1;
        o0.x = acc[i][0] + bvals[0]; o0.y = acc[i][1] + bvals[1];
        o0.z = acc[i][2] + bvals[2]; o0.w = acc[i][3] + bvals[3];
        o1.x = acc[i][4] + bvals[4]; o1.y = acc[i][5] + bvals[5];
        o1.z = acc[i][6] + bvals[6]; o1.w = acc[i][7] + bvals[7];
        *(float4*)&C[(size_t)row * N + bn * 128 + tx * 4]      = o0;
        *(float4*)&C[(size_t)row * N + bn * 128 + 64 + tx * 4] = o1;
    }
}

// ---------------- recurrence: K-packed shfl outer product + L2 tag exchange ----
// 128 CTAs = 16 groups (batch pairs) x 8 ranks. Rank j owns 128 gate-columns
// colg(c) = (c>>5)*256 + j*32 + (c&31). Warp w owns K-slice [32w, +32).
// Lanes 0-15 hold the slice's h as 16 u64 K-pairs (coalesced LDS.64); the pair
// is shuffled (2 SASS SHFL) and consumed directly by FFMA2 with K-packed
// weights w2k[16][4] (128 regs): 16x(4 SHFL + 8 FFMA2) = 192 slots/step/lane
// vs R10's 320. No pack MOVs, no broadcast LDS.
// Reduce: STS red[8][2][128]; ONE barrier; act threads (tid<64) sum the 8
// partials per gate inline (32 LDS), LSTM math via MUFU.TANH, tagged store.
// Exchange = R7/R10: {h, tag} 8B relaxed atomics, self-validating; all threads
// poll their own two words; 2 barriers/step total.
__global__ void __launch_bounds__(256, 1) lstm_rec(const float* __restrict__ Wh)
{
    const int cta  = blockIdx.x;
    const int grp  = cta >> 3;
    const int j    = cta & 7;
    const int b0   = grp * 2;
    const int tid  = threadIdx.x;
    const int w    = tid >> 5;
    const int lane = tid & 31;

    __shared__ __align__(16) float hs[2][256];        // batch x h
    __shared__ __align__(16) float red[8][2][128];    // warp x batch x col
    __shared__ float csm[2][32];

    // persistent K-packed weights: lane owns cols c0..c0+3 (c0 = 4*lane),
    // w2k[k2][cc] = (Wh[32w+2k2][cg+cc], Wh[32w+2k2+1][cg+cc])
    const int c0  = 4 * lane;
    const int cg0 = (c0 >> 5) * 256 + j * 32 + (c0 & 31);   // 4 adjacent cols
    unsigned long long w2k[16][4];
    {
#pragma unroll
        for (int k2 = 0; k2 < 16; k2++) {
            const float* r0 = Wh + (size_t)(32 * w + 2 * k2) * G4 + cg0;
            const float* r1 = r0 + G4;
#pragma unroll
            for (int cc = 0; cc < 4; cc++)
                w2k[k2][cc] = pk2(__ldg(&r0[cc]), __ldg(&r1[cc]));
        }
    }

    hs[0][tid] = 0.f;
    hs[1][tid] = 0.f;
    if (tid < 64) csm[tid >> 5][tid & 31] = 0.f;
    __syncthreads();

    // act-thread xg prefetch for t=0 (act thread: bb=tid>>5, ll=tid&31)
    const int bb = tid >> 5;
    const int ll = tid & 31;
    float xq0 = 0.f, xq1 = 0.f, xq2 = 0.f, xq3 = 0.f;
    if (tid < 64) {
        const float* xp = g_xg + ((size_t)((b0 + bb) * TT)) * G4 + j * 32 + ll;
        xq0 = __ldg(xp);
        xq1 = __ldg(xp + 256);
        xq2 = __ldg(xp + 512);
        xq3 = __ldg(xp + 768);
    }

    const int hl = lane & 15;   // u64 K-pair index held by this lane

    for (int t = 0; t < TT; t++) {
        // ---- K-packed partial GEMV over this warp's K-slice ----
        const unsigned long long hp0 =
            ((const unsigned long long*)&hs[0][32 * w])[hl];   // coalesced LDS.64
        const unsigned long long hp1 =
            ((const unsigned long long*)&hs[1][32 * w])[hl];

        unsigned long long ac0[4] = {0ull, 0ull, 0ull, 0ull};  // batch0, 4 cols
        unsigned long long ac1[4] = {0ull, 0ull, 0ull, 0ull};  // batch1
#pragma unroll
        for (int k2 = 0; k2 < 16; k2++) {
            const unsigned long long h0 = __shfl_sync(0xffffffffu, hp0, k2);
            const unsigned long long h1 = __shfl_sync(0xffffffffu, hp1, k2);
            ac0[0] = ffma2(w2k[k2][0], h0, ac0[0]);
            ac0[1] = ffma2(w2k[k2][1], h0, ac0[1]);
            ac0[2] = ffma2(w2k[k2][2], h0, ac0[2]);
            ac0[3] = ffma2(w2k[k2][3], h0, ac0[3]);
            ac1[0] = ffma2(w2k[k2][0], h1, ac1[0]);
            ac1[1] = ffma2(w2k[k2][1], h1, ac1[1]);
            ac1[2] = ffma2(w2k[k2][2], h1, ac1[2]);
            ac1[3] = ffma2(w2k[k2][3], h1, ac1[3]);
        }
        {
            float4 r0, r1;
            float2 u;
            u = unpk2(ac0[0]); r0.x = u.x + u.y;
            u = unpk2(ac0[1]); r0.y = u.x + u.y;
            u = unpk2(ac0[2]); r0.z = u.x + u.y;
            u = unpk2(ac0[3]); r0.w = u.x + u.y;
            u = unpk2(ac1[0]); r1.x = u.x + u.y;
            u = unpk2(ac1[1]); r1.y = u.x + u.y;
            u = unpk2(ac1[2]); r1.z = u.x + u.y;
            u = unpk2(ac1[3]); r1.w = u.x + u.y;
            *(float4*)&red[w][0][c0] = r0;
            *(float4*)&red[w][1][c0] = r1;
        }
        __syncthreads();   // red ready; also: all hs reads of this step done

        const int   sl   = (t + 1) & 1;
        const float tagf = (float)(t + 1);

        // ---- inline reduce + activation: 64 threads = 2 batches x 32 h ----
        if (tid < 64) {
            float gi = xq0, gf = xq1, gg = xq2, go = xq3;
#pragma unroll
            for (int r = 0; r < 8; r++) {
                gi += red[r][bb][ll];
                gf += red[r][bb][32 + ll];
                gg += red[r][bb][64 + ll];
                go += red[r][bb][96 + ll];
            }
            const float cprev = csm[bb][ll];
            const float si = sigap(gi);
            const float sf = sigap(gf);
            const float so = sigap(go);
            const float tg = tanhap(gg);
            const float cn = sf * cprev + si * tg;
            const float hn = so * tanhap(cn);
            csm[bb][ll] = cn;
            const int hidx = j * 32 + ll;
            if (t + 1 < TT)
                st_rlx64(&g_hx[sl][grp][hidx][bb], pk2(hn, tagf));
            g_hseq[((size_t)((b0 + bb) * TT + t)) * HH + hidx] = hn;
        }
        // NO barrier: warps 2-7 go straight to polling while warps 0-1 finish

        if (t + 1 < TT) {
            // prefetch next xg (in flight during the poll)
            if (tid < 64) {
                const float* xp = g_xg + ((size_t)((b0 + bb) * TT + (t + 1))) * G4
                                + j * 32 + ll;
                xq0 = __ldg(xp);
                xq1 = __ldg(xp + 256);
                xq2 = __ldg(xp + 512);
                xq3 = __ldg(xp + 768);
            }
            // each thread polls its OWN two tagged words; hit == data
            const unsigned long long* src = &g_hx[sl][grp][tid][0];
            float2 d0, d1;
            for (;;) {
                const unsigned long long v0 = ld_rlx64(src);
                const unsigned long long v1 = ld_rlx64(src + 1);
                d0 = unpk2(v0);
                d1 = unpk2(v1);
                if (d0.y >= tagf && d1.y >= tagf) break;
            }
            hs[0][tid] = d0.x;
            hs[1][tid] = d1.x;
            __syncthreads();
        }
    }
}

// ---------------- launch ----------------
extern "C" void kernel_launch(void* const* d_in, const int* in_sizes, int n_in,
                              void* d_out, int out_size)
{
    const float* x  = (const float*)d_in[0];   // [B,T,DIN]
    const float* Wx = (const float*)d_in[1];   // [DIN,4H]
    const float* Wh = (const float*)d_in[2];   // [H,4H]
    const float* b  = (const float*)d_in[3];   // [4H]
    const float* Wo = (const float*)d_in[4];   // [H,DOUT]
    const float* bo = (const float*)d_in[5];   // [DOUT]
    float* out = (float*)d_out;                // [B,T,DOUT]

    float *xg_ptr = nullptr, *hseq_ptr = nullptr;
    cudaGetSymbolAddress((void**)&xg_ptr, g_xg);
    cudaGetSymbolAddress((void**)&hseq_ptr, g_hseq);

    // reset exchange tags (graph replays reuse device state)
    init_kernel<<<64, 256>>>();

    // 1) xg = x @ Wx + b : [131072,256] @ [256,1024]
    {
        dim3 grid(G4 / 128, (BB * TT) / 128);   // (8, 1024)
        sgemm_bias_128<<<grid, 256>>>(x, Wx, b, xg_ptr, BB * TT, G4, DIN);
    }

    // 2) recurrence over 4096 steps (16 groups x 8 CTAs, all co-resident)
    lstm_rec<<<128, 256>>>(Wh);

    // 3) out = hseq @ Wo + bo : [131072,256] @ [256,256]
    {
        dim3 grid(256 / 128, (BB * TT) / 128);  // (2, 1024)
        sgemm_bias_128<<<grid, 256>>>(hseq_ptr, Wo, bo, out, BB * TT, 256, HH);
    }
}